// round 3
// baseline (speedup 1.0000x reference)
#include <cuda_runtime.h>
#include <cstdint>
#include <cstddef>

// ============================================================================
// Problem constants and scratch
// ============================================================================
static constexpr int DIM   = 1024;
static constexpr int H_MID = 512;
static constexpr int H_LOW = 256;
static constexpr int MTOT  = 4 * 8192;  // 32768 tokens

__device__ float g_buf0[(size_t)MTOT * DIM];    // ln_out, later h2
__device__ float g_buf1[(size_t)MTOT * H_MID];  // h1, later h3
__device__ float g_w1t[H_MID * DIM];
__device__ float g_w2t[H_MID * H_MID];
__device__ float g_w3t[H_LOW * H_MID];
__device__ float g_w4t[DIM * H_LOW];

// ============================================================================
// Small helpers
// ============================================================================

// fp32 -> tf32 round-to-nearest (value kept in f32 container, low 13 bits 0).
__device__ __forceinline__ float to_tf32(float v) {
    uint32_t r;
    asm("cvt.rna.tf32.f32 %0, %1;" : "=r"(r) : "f"(v));
    return __uint_as_float(r);
}

__device__ __forceinline__ float gelu_exact(float v) {
    return 0.5f * v * (1.0f + erff(v * 0.70710678118654752440f));
}

// K-dim storage permutation (within each group of 8): logical k stored at p8(k).
// Makes the mma.sync tf32 fragment pair (k, k+4) contiguous -> ld.shared.v2.f32.
__device__ __forceinline__ int p8(int k) {
    return (k & ~7) | ((k & 3) << 1) | ((k >> 2) & 1);
}

__device__ __forceinline__ uint32_t smem_to_u32(const void* p) {
    uint32_t a;
    asm("{ .reg .u64 t; cvta.to.shared.u64 t, %1; cvt.u32.u64 %0, t; }"
        : "=r"(a) : "l"(p));
    return a;
}

__device__ __forceinline__ void cp_async16(uint32_t s, const void* g) {
    asm volatile("cp.async.cg.shared.global [%0], [%1], 16;"
                 :: "r"(s), "l"(g));
}

__device__ __forceinline__ void mma_tf32(float (&d)[4], const uint32_t (&a)[4],
                                         const uint32_t (&b)[2]) {
    asm volatile(
        "mma.sync.aligned.m16n8k8.row.col.f32.tf32.tf32.f32 "
        "{%0,%1,%2,%3},{%4,%5,%6,%7},{%8,%9},{%0,%1,%2,%3};"
        : "+f"(d[0]), "+f"(d[1]), "+f"(d[2]), "+f"(d[3])
        : "r"(a[0]), "r"(a[1]), "r"(a[2]), "r"(a[3]),
          "r"(b[0]), "r"(b[1]));
}

// ============================================================================
// Weight transpose + tf32 round + K-perm:  W[K,N] -> Wt[N, p8(K)]
// ============================================================================
__global__ void transpose_tf32_kernel(const float* __restrict__ W,
                                      float* __restrict__ Wt, int K, int N) {
    __shared__ float tile[32][33];
    const int n0 = blockIdx.x * 32, k0 = blockIdx.y * 32;
    const int tx = threadIdx.x, ty = threadIdx.y;  // 32 x 8
#pragma unroll
    for (int j = 0; j < 32; j += 8)
        tile[ty + j][tx] = W[(size_t)(k0 + ty + j) * N + n0 + tx];
    __syncthreads();
#pragma unroll
    for (int j = 0; j < 32; j += 8)
        Wt[(size_t)(n0 + ty + j) * K + p8(k0 + tx)] = to_tf32(tile[tx][ty + j]);
}

// ============================================================================
// LayerNorm over 1024-wide rows; output tf32-rounded and K-permuted
// ============================================================================
__global__ void __launch_bounds__(256) ln_kernel(const float* __restrict__ x,
                                                 const float* __restrict__ gamma,
                                                 const float* __restrict__ beta,
                                                 float* __restrict__ y) {
    __shared__ float red_s[8], red_q[8];
    const int row = blockIdx.x;
    const int t = threadIdx.x;
    const float4 v = (reinterpret_cast<const float4*>(x) + (size_t)row * 256)[t];
    float s = v.x + v.y + v.z + v.w;
    float q = v.x * v.x + v.y * v.y + v.z * v.z + v.w * v.w;
#pragma unroll
    for (int o = 16; o; o >>= 1) {
        s += __shfl_xor_sync(0xffffffffu, s, o);
        q += __shfl_xor_sync(0xffffffffu, q, o);
    }
    if ((t & 31) == 0) { red_s[t >> 5] = s; red_q[t >> 5] = q; }
    __syncthreads();
    float st = 0.f, qt = 0.f;
#pragma unroll
    for (int i = 0; i < 8; i++) { st += red_s[i]; qt += red_q[i]; }
    const float mu = st * (1.0f / 1024.0f);
    const float var = qt * (1.0f / 1024.0f) - mu * mu;
    const float rstd = rsqrtf(var + 1e-5f);
    const float4 g = reinterpret_cast<const float4*>(gamma)[t];
    const float4 b = reinterpret_cast<const float4*>(beta)[t];
    float* yr = y + (size_t)row * 1024;
    const int c = 4 * t;
    yr[p8(c + 0)] = to_tf32((v.x - mu) * rstd * g.x + b.x);
    yr[p8(c + 1)] = to_tf32((v.y - mu) * rstd * g.y + b.y);
    yr[p8(c + 2)] = to_tf32((v.z - mu) * rstd * g.z + b.z);
    yr[p8(c + 3)] = to_tf32((v.w - mu) * rstd * g.w + b.w);
}

// ============================================================================
// tf32 mma.sync GEMM:  C[128 x 128 tile] = A[M,K] @ Bt[N,K]^T (+bias, epilogue)
//   128 threads (4 warps, 2x2), warp tile 64x64, K-tile 32, cp.async 2-stage.
//   A and Bt are stored with p8-permuted K columns.
//   RESID=false: out[p8 cols] = tf32(gelu(acc + bias))   (feeds next GEMM)
//   RESID=true : out = acc + bias + resid                (final fp32)
// ============================================================================
static constexpr int LDS_PITCH = 40;            // floats per smem row (160 B)
static constexpr int STAGE_FLT = 2 * 128 * LDS_PITCH;  // A + B, one stage
static constexpr int GEMM_SMEM = 2 * STAGE_FLT * 4;    // bytes, double buffer

template <bool RESID>
__global__ void __launch_bounds__(128) gemm_tf32_kernel(
    const float* __restrict__ A, const float* __restrict__ Bt,
    const float* __restrict__ bias, const float* __restrict__ resid,
    float* __restrict__ C, int K, int Ntot) {
    extern __shared__ float sm[];
    const uint32_t smem_u = smem_to_u32(sm);
    const int tid = threadIdx.x;
    const int wid = tid >> 5, lane = tid & 31;
    const int wm = wid & 1, wn = wid >> 1;      // 2x2 warps
    const int m0 = blockIdx.x * 128, n0 = blockIdx.y * 128;
    const int NK = K >> 5;

    const float* Abase = A + (size_t)m0 * K;
    const float* Bbase = Bt + (size_t)n0 * K;

    auto load_tile = [&](int kt, int buf) {
        const uint32_t sb = smem_u + (uint32_t)buf * (STAGE_FLT * 4);
        const int ko = kt * 32;
#pragma unroll
        for (int i = 0; i < 8; i++) {
            const int idx = tid + i * 128;
            const int row = idx >> 3, ch = idx & 7;
            cp_async16(sb + (uint32_t)(row * 160 + ch * 16),
                       Abase + (size_t)row * K + ko + ch * 4);
        }
#pragma unroll
        for (int i = 0; i < 8; i++) {
            const int idx = tid + i * 128;
            const int row = idx >> 3, ch = idx & 7;
            cp_async16(sb + (uint32_t)(128 * 160) + (uint32_t)(row * 160 + ch * 16),
                       Bbase + (size_t)row * K + ko + ch * 4);
        }
        asm volatile("cp.async.commit_group;" ::: "memory");
    };

    float d[4][8][4];
#pragma unroll
    for (int i = 0; i < 4; i++)
#pragma unroll
        for (int j = 0; j < 8; j++)
#pragma unroll
            for (int e = 0; e < 4; e++) d[i][j][e] = 0.0f;

    load_tile(0, 0);

    const int r = lane >> 2;            // 0..7
    const int q2 = (lane & 3) * 2;      // permuted col offset of (k, k+4) pair

    for (int kt = 0; kt < NK; kt++) {
        if (kt + 1 < NK) {
            load_tile(kt + 1, (kt + 1) & 1);
            asm volatile("cp.async.wait_group 1;" ::: "memory");
        } else {
            asm volatile("cp.async.wait_group 0;" ::: "memory");
        }
        __syncthreads();
        const float* As = sm + (kt & 1) * STAGE_FLT;
        const float* Bs = As + 128 * LDS_PITCH;
#pragma unroll
        for (int ks = 0; ks < 4; ks++) {
            const int kk = ks * 8;
            uint32_t a[4][4], b[8][2];
#pragma unroll
            for (int i = 0; i < 4; i++) {
                const float2 lo = *reinterpret_cast<const float2*>(
                    As + (wm * 64 + i * 16 + r) * LDS_PITCH + kk + q2);
                const float2 hi = *reinterpret_cast<const float2*>(
                    As + (wm * 64 + i * 16 + 8 + r) * LDS_PITCH + kk + q2);
                a[i][0] = __float_as_uint(lo.x); a[i][2] = __float_as_uint(lo.y);
                a[i][1] = __float_as_uint(hi.x); a[i][3] = __float_as_uint(hi.y);
            }
#pragma unroll
            for (int j = 0; j < 8; j++) {
                const float2 bv = *reinterpret_cast<const float2*>(
                    Bs + (wn * 64 + j * 8 + r) * LDS_PITCH + kk + q2);
                b[j][0] = __float_as_uint(bv.x); b[j][1] = __float_as_uint(bv.y);
            }
#pragma unroll
            for (int i = 0; i < 4; i++)
#pragma unroll
                for (int j = 0; j < 8; j++) mma_tf32(d[i][j], a[i], b[j]);
        }
        __syncthreads();
    }

    // ---- Epilogue ----
#pragma unroll
    for (int i = 0; i < 4; i++) {
        const int r0 = m0 + wm * 64 + i * 16 + (lane >> 2);
#pragma unroll
        for (int j = 0; j < 8; j++) {
            const int cl = wn * 64 + j * 8 + (lane & 3) * 2;  // logical col in tile
            const int cg = n0 + cl;
            const float bx = bias[cg], by = bias[cg + 1];
            float v0 = d[i][j][0] + bx, v1 = d[i][j][1] + by;
            float v2 = d[i][j][2] + bx, v3 = d[i][j][3] + by;
            if (RESID) {
                const float2 x0 = *reinterpret_cast<const float2*>(
                    resid + (size_t)r0 * Ntot + cg);
                const float2 x1 = *reinterpret_cast<const float2*>(
                    resid + (size_t)(r0 + 8) * Ntot + cg);
                *reinterpret_cast<float2*>(C + (size_t)r0 * Ntot + cg) =
                    make_float2(v0 + x0.x, v1 + x0.y);
                *reinterpret_cast<float2*>(C + (size_t)(r0 + 8) * Ntot + cg) =
                    make_float2(v2 + x1.x, v3 + x1.y);
            } else {
                const int s0 = n0 + p8(cl), s1 = n0 + p8(cl + 1);
                C[(size_t)r0 * Ntot + s0] = to_tf32(gelu_exact(v0));
                C[(size_t)r0 * Ntot + s1] = to_tf32(gelu_exact(v1));
                C[(size_t)(r0 + 8) * Ntot + s0] = to_tf32(gelu_exact(v2));
                C[(size_t)(r0 + 8) * Ntot + s1] = to_tf32(gelu_exact(v3));
            }
        }
    }
}

// ============================================================================
// kernel_launch
// ============================================================================
extern "C" void kernel_launch(void* const* d_in, const int* in_sizes, int n_in,
                              void* d_out, int out_size) {
    const float* x     = (const float*)d_in[0];
    const float* gamma = (const float*)d_in[1];
    const float* beta  = (const float*)d_in[2];
    const float* W1    = (const float*)d_in[3];
    const float* b1    = (const float*)d_in[4];
    const float* W2    = (const float*)d_in[5];
    const float* b2    = (const float*)d_in[6];
    const float* W3    = (const float*)d_in[7];
    const float* b3    = (const float*)d_in[8];
    const float* W4    = (const float*)d_in[9];
    const float* b4    = (const float*)d_in[10];

    float *buf0, *buf1, *w1t, *w2t, *w3t, *w4t;
    cudaGetSymbolAddress((void**)&buf0, g_buf0);
    cudaGetSymbolAddress((void**)&buf1, g_buf1);
    cudaGetSymbolAddress((void**)&w1t, g_w1t);
    cudaGetSymbolAddress((void**)&w2t, g_w2t);
    cudaGetSymbolAddress((void**)&w3t, g_w3t);
    cudaGetSymbolAddress((void**)&w4t, g_w4t);

    cudaFuncSetAttribute(gemm_tf32_kernel<false>,
                         cudaFuncAttributeMaxDynamicSharedMemorySize, GEMM_SMEM);
    cudaFuncSetAttribute(gemm_tf32_kernel<true>,
                         cudaFuncAttributeMaxDynamicSharedMemorySize, GEMM_SMEM);

    const dim3 tb(32, 8);
    transpose_tf32_kernel<<<dim3(H_MID / 32, DIM / 32),   tb>>>(W1, w1t, DIM,   H_MID);
    transpose_tf32_kernel<<<dim3(H_MID / 32, H_MID / 32), tb>>>(W2, w2t, H_MID, H_MID);
    transpose_tf32_kernel<<<dim3(H_LOW / 32, H_MID / 32), tb>>>(W3, w3t, H_MID, H_LOW);
    transpose_tf32_kernel<<<dim3(DIM / 32,   H_LOW / 32), tb>>>(W4, w4t, H_LOW, DIM);

    ln_kernel<<<MTOT, 256>>>(x, gamma, beta, buf0);

    // h1 = gelu(ln @ W1 + b1)   (32768 x 512), K=1024
    gemm_tf32_kernel<false><<<dim3(MTOT / 128, H_MID / 128), 128, GEMM_SMEM>>>(
        buf0, w1t, b1, nullptr, buf1, DIM, H_MID);
    // h2 = gelu(h1 @ W2 + b2)   (32768 x 512), K=512
    gemm_tf32_kernel<false><<<dim3(MTOT / 128, H_MID / 128), 128, GEMM_SMEM>>>(
        buf1, w2t, b2, nullptr, buf0, H_MID, H_MID);
    // h3 = gelu(h2 @ W3 + b3)   (32768 x 256), K=512
    gemm_tf32_kernel<false><<<dim3(MTOT / 128, H_LOW / 128), 128, GEMM_SMEM>>>(
        buf0, w3t, b3, nullptr, buf1, H_MID, H_LOW);
    // out = x + h3 @ W4 + b4    (32768 x 1024), K=256
    gemm_tf32_kernel<true><<<dim3(MTOT / 128, DIM / 128), 128, GEMM_SMEM>>>(
        buf1, w4t, b4, x, (float*)d_out, H_LOW, DIM);
}

// round 4
// speedup vs baseline: 1.6766x; 1.6766x over previous
#include <cuda_runtime.h>
#include <cuda_bf16.h>
#include <cstdint>
#include <cstddef>

// ============================================================================
// Problem constants and scratch
// ============================================================================
static constexpr int DIM   = 1024;
static constexpr int H_MID = 512;
static constexpr int H_LOW = 256;
static constexpr int MTOT  = 4 * 8192;  // 32768 tokens

__device__ __nv_bfloat16 g_a0[(size_t)MTOT * DIM];    // ln_out, later h2
__device__ __nv_bfloat16 g_a1[(size_t)MTOT * H_MID];  // h1, later h3
__device__ __nv_bfloat16 g_w1t[H_MID * DIM];
__device__ __nv_bfloat16 g_w2t[H_MID * H_MID];
__device__ __nv_bfloat16 g_w3t[H_LOW * H_MID];
__device__ __nv_bfloat16 g_w4t[DIM * H_LOW];

// ============================================================================
// Helpers
// ============================================================================
__device__ __forceinline__ float gelu_exact(float v) {
    return 0.5f * v * (1.0f + erff(v * 0.70710678118654752440f));
}

__device__ __forceinline__ uint32_t smem_to_u32(const void* p) {
    uint32_t a;
    asm("{ .reg .u64 t; cvta.to.shared.u64 t, %1; cvt.u32.u64 %0, t; }"
        : "=r"(a) : "l"(p));
    return a;
}

__device__ __forceinline__ void cp_async16(uint32_t s, const void* g) {
    asm volatile("cp.async.cg.shared.global [%0], [%1], 16;" :: "r"(s), "l"(g));
}

__device__ __forceinline__ void ldsm_x4(uint32_t (&r)[4], uint32_t addr) {
    asm volatile("ldmatrix.sync.aligned.m8n8.x4.shared.b16 {%0,%1,%2,%3}, [%4];"
                 : "=r"(r[0]), "=r"(r[1]), "=r"(r[2]), "=r"(r[3]) : "r"(addr));
}

__device__ __forceinline__ void mma_bf16(float (&d)[4], const uint32_t (&a)[4],
                                         uint32_t b0, uint32_t b1) {
    asm volatile(
        "mma.sync.aligned.m16n8k16.row.col.f32.bf16.bf16.f32 "
        "{%0,%1,%2,%3},{%4,%5,%6,%7},{%8,%9},{%0,%1,%2,%3};"
        : "+f"(d[0]), "+f"(d[1]), "+f"(d[2]), "+f"(d[3])
        : "r"(a[0]), "r"(a[1]), "r"(a[2]), "r"(a[3]), "r"(b0), "r"(b1));
}

// ============================================================================
// Weight transpose + bf16 round:  W[K,N] fp32 -> Wt[N,K] bf16
// ============================================================================
__global__ void transpose_bf16_kernel(const float* __restrict__ W,
                                      __nv_bfloat16* __restrict__ Wt,
                                      int K, int N) {
    __shared__ float tile[32][33];
    const int n0 = blockIdx.x * 32, k0 = blockIdx.y * 32;
    const int tx = threadIdx.x, ty = threadIdx.y;  // 32 x 8
#pragma unroll
    for (int j = 0; j < 32; j += 8)
        tile[ty + j][tx] = W[(size_t)(k0 + ty + j) * N + n0 + tx];
    __syncthreads();
#pragma unroll
    for (int j = 0; j < 32; j += 8)
        Wt[(size_t)(n0 + ty + j) * K + k0 + tx] =
            __float2bfloat16_rn(tile[tx][ty + j]);
}

// ============================================================================
// LayerNorm over 1024-wide rows; bf16 output
// ============================================================================
__global__ void __launch_bounds__(256) ln_kernel(const float* __restrict__ x,
                                                 const float* __restrict__ gamma,
                                                 const float* __restrict__ beta,
                                                 __nv_bfloat16* __restrict__ y) {
    __shared__ float red_s[8], red_q[8];
    const int row = blockIdx.x;
    const int t = threadIdx.x;
    const float4 v = (reinterpret_cast<const float4*>(x) + (size_t)row * 256)[t];
    float s = v.x + v.y + v.z + v.w;
    float q = v.x * v.x + v.y * v.y + v.z * v.z + v.w * v.w;
#pragma unroll
    for (int o = 16; o; o >>= 1) {
        s += __shfl_xor_sync(0xffffffffu, s, o);
        q += __shfl_xor_sync(0xffffffffu, q, o);
    }
    if ((t & 31) == 0) { red_s[t >> 5] = s; red_q[t >> 5] = q; }
    __syncthreads();
    float st = 0.f, qt = 0.f;
#pragma unroll
    for (int i = 0; i < 8; i++) { st += red_s[i]; qt += red_q[i]; }
    const float mu = st * (1.0f / 1024.0f);
    const float var = qt * (1.0f / 1024.0f) - mu * mu;
    const float rstd = rsqrtf(var + 1e-5f);
    const float4 g = reinterpret_cast<const float4*>(gamma)[t];
    const float4 b = reinterpret_cast<const float4*>(beta)[t];
    __nv_bfloat162 h01, h23;
    h01.x = __float2bfloat16_rn((v.x - mu) * rstd * g.x + b.x);
    h01.y = __float2bfloat16_rn((v.y - mu) * rstd * g.y + b.y);
    h23.x = __float2bfloat16_rn((v.z - mu) * rstd * g.z + b.z);
    h23.y = __float2bfloat16_rn((v.w - mu) * rstd * g.w + b.w);
    uint2 pk;
    pk.x = *reinterpret_cast<uint32_t*>(&h01);
    pk.y = *reinterpret_cast<uint32_t*>(&h23);
    (reinterpret_cast<uint2*>(y + (size_t)row * 1024))[t] = pk;
}

// ============================================================================
// bf16 mma.sync GEMM:  C[128x128 tile] = A[M,K] @ Bt[N,K]^T (+bias, epilogue)
//   256 threads, 8 warps (4x2), warp tile 32x64, K-tile 64, 2-stage cp.async.
//   Fragments via ldmatrix.x4; smem pitch 144B (conflict-free ldmatrix).
//   RESID=false: out bf16 = gelu(acc + bias)   (feeds next GEMM)
//   RESID=true : out fp32 = acc + bias + resid (final output)
// ============================================================================
static constexpr int PITCH = 144;                       // bytes per smem row
static constexpr int BOFF = 128 * PITCH;                // B tile offset in stage
static constexpr int STAGE_BYTES = 2 * 128 * PITCH;     // 36864
static constexpr int GEMM_SMEM = 2 * STAGE_BYTES;       // 73728

template <bool RESID>
__global__ void __launch_bounds__(256, 2) gemm_bf16_kernel(
    const __nv_bfloat16* __restrict__ A, const __nv_bfloat16* __restrict__ Bt,
    const float* __restrict__ bias, const float* __restrict__ resid,
    void* __restrict__ Cv, int K, int Ntot) {
    extern __shared__ char smem[];
    const uint32_t smem_u = smem_to_u32(smem);
    const int tid = threadIdx.x;
    const int wid = tid >> 5, lane = tid & 31;
    const int wm = wid & 3, wn = wid >> 2;      // 4x2 warps, warp tile 32x64
    const int m0 = blockIdx.x * 128, n0 = blockIdx.y * 128;
    const int NK = K >> 6;                      // K tiles of 64

    const __nv_bfloat16* Abase = A + (size_t)m0 * K;
    const __nv_bfloat16* Bbase = Bt + (size_t)n0 * K;

    // cp.async indices: thread covers 4 chunks of A and 4 of B per K-tile
    const int ldrow = tid >> 3, ldc = (tid & 7) * 16;  // ldc in bytes (8 bf16)
    auto load_tile = [&](int kt, int buf) {
        const uint32_t sb = smem_u + (uint32_t)buf * STAGE_BYTES;
        const int ko = kt * 64;
#pragma unroll
        for (int i = 0; i < 4; i++) {
            const int row = ldrow + i * 32;
            cp_async16(sb + (uint32_t)(row * PITCH) + ldc,
                       Abase + (size_t)row * K + ko + (ldc >> 1));
        }
#pragma unroll
        for (int i = 0; i < 4; i++) {
            const int row = ldrow + i * 32;
            cp_async16(sb + (uint32_t)BOFF + (uint32_t)(row * PITCH) + ldc,
                       Bbase + (size_t)row * K + ko + (ldc >> 1));
        }
        asm volatile("cp.async.commit_group;" ::: "memory");
    };

    float d[2][8][4];
#pragma unroll
    for (int i = 0; i < 2; i++)
#pragma unroll
        for (int j = 0; j < 8; j++)
#pragma unroll
            for (int e = 0; e < 4; e++) d[i][j][e] = 0.0f;

    // Per-lane ldmatrix row offsets (bytes within a stage)
    // A x4: lanes 0-7 rows m..m+7 @k, 8-15 rows m+8..15 @k,
    //       16-23 rows m..m+7 @k+16B, 24-31 rows m+8..15 @k+16B
    const uint32_t aOff = (uint32_t)((wm * 32 + (lane & 15)) * PITCH +
                                     ((lane >> 4) & 1) * 16);
    // B x4: lanes 0-7 rows n..n+7 @k, 8-15 rows n..n+7 @k+16B,
    //       16-23 rows n+8..15 @k, 24-31 rows n+8..15 @k+16B
    const uint32_t bOff = (uint32_t)BOFF +
        (uint32_t)((wn * 64 + (lane & 7) + ((lane >> 4) & 1) * 8) * PITCH +
                   ((lane >> 3) & 1) * 16);

    load_tile(0, 0);

    for (int kt = 0; kt < NK; kt++) {
        if (kt + 1 < NK) {
            load_tile(kt + 1, (kt + 1) & 1);
            asm volatile("cp.async.wait_group 1;" ::: "memory");
        } else {
            asm volatile("cp.async.wait_group 0;" ::: "memory");
        }
        __syncthreads();
        const uint32_t sb = smem_u + (uint32_t)(kt & 1) * STAGE_BYTES;
#pragma unroll
        for (int ks = 0; ks < 4; ks++) {        // 4 x k16 within the 64-K tile
            uint32_t a[2][4], b[4][4];
#pragma unroll
            for (int i = 0; i < 2; i++)
                ldsm_x4(a[i], sb + aOff + (uint32_t)(i * 16 * PITCH + ks * 32));
#pragma unroll
            for (int j2 = 0; j2 < 4; j2++)
                ldsm_x4(b[j2], sb + bOff + (uint32_t)(j2 * 16 * PITCH + ks * 32));
#pragma unroll
            for (int i = 0; i < 2; i++)
#pragma unroll
                for (int j2 = 0; j2 < 4; j2++) {
                    mma_bf16(d[i][2 * j2],     a[i], b[j2][0], b[j2][1]);
                    mma_bf16(d[i][2 * j2 + 1], a[i], b[j2][2], b[j2][3]);
                }
        }
        __syncthreads();
    }

    // ---- Epilogue ----
    const int g = lane >> 2, t2 = (lane & 3) * 2;
#pragma unroll
    for (int i = 0; i < 2; i++) {
        const int r0 = m0 + wm * 32 + i * 16 + g;
#pragma unroll
        for (int j = 0; j < 8; j++) {
            const int cg = n0 + wn * 64 + j * 8 + t2;
            const float bx = bias[cg], by = bias[cg + 1];
            float v0 = d[i][j][0] + bx, v1 = d[i][j][1] + by;
            float v2 = d[i][j][2] + bx, v3 = d[i][j][3] + by;
            if (RESID) {
                float* C = (float*)Cv;
                const float2 x0 = *reinterpret_cast<const float2*>(
                    resid + (size_t)r0 * Ntot + cg);
                const float2 x1 = *reinterpret_cast<const float2*>(
                    resid + (size_t)(r0 + 8) * Ntot + cg);
                *reinterpret_cast<float2*>(C + (size_t)r0 * Ntot + cg) =
                    make_float2(v0 + x0.x, v1 + x0.y);
                *reinterpret_cast<float2*>(C + (size_t)(r0 + 8) * Ntot + cg) =
                    make_float2(v2 + x1.x, v3 + x1.y);
            } else {
                __nv_bfloat16* C = (__nv_bfloat16*)Cv;
                __nv_bfloat162 p0, p1;
                p0.x = __float2bfloat16_rn(gelu_exact(v0));
                p0.y = __float2bfloat16_rn(gelu_exact(v1));
                p1.x = __float2bfloat16_rn(gelu_exact(v2));
                p1.y = __float2bfloat16_rn(gelu_exact(v3));
                *reinterpret_cast<__nv_bfloat162*>(C + (size_t)r0 * Ntot + cg) = p0;
                *reinterpret_cast<__nv_bfloat162*>(C + (size_t)(r0 + 8) * Ntot + cg) = p1;
            }
        }
    }
}

// ============================================================================
// kernel_launch
// ============================================================================
extern "C" void kernel_launch(void* const* d_in, const int* in_sizes, int n_in,
                              void* d_out, int out_size) {
    const float* x     = (const float*)d_in[0];
    const float* gamma = (const float*)d_in[1];
    const float* beta  = (const float*)d_in[2];
    const float* W1    = (const float*)d_in[3];
    const float* b1    = (const float*)d_in[4];
    const float* W2    = (const float*)d_in[5];
    const float* b2    = (const float*)d_in[6];
    const float* W3    = (const float*)d_in[7];
    const float* b3    = (const float*)d_in[8];
    const float* W4    = (const float*)d_in[9];
    const float* b4    = (const float*)d_in[10];

    __nv_bfloat16 *a0, *a1, *w1t, *w2t, *w3t, *w4t;
    cudaGetSymbolAddress((void**)&a0, g_a0);
    cudaGetSymbolAddress((void**)&a1, g_a1);
    cudaGetSymbolAddress((void**)&w1t, g_w1t);
    cudaGetSymbolAddress((void**)&w2t, g_w2t);
    cudaGetSymbolAddress((void**)&w3t, g_w3t);
    cudaGetSymbolAddress((void**)&w4t, g_w4t);

    cudaFuncSetAttribute(gemm_bf16_kernel<false>,
                         cudaFuncAttributeMaxDynamicSharedMemorySize, GEMM_SMEM);
    cudaFuncSetAttribute(gemm_bf16_kernel<true>,
                         cudaFuncAttributeMaxDynamicSharedMemorySize, GEMM_SMEM);

    const dim3 tb(32, 8);
    transpose_bf16_kernel<<<dim3(H_MID / 32, DIM / 32),   tb>>>(W1, w1t, DIM,   H_MID);
    transpose_bf16_kernel<<<dim3(H_MID / 32, H_MID / 32), tb>>>(W2, w2t, H_MID, H_MID);
    transpose_bf16_kernel<<<dim3(H_LOW / 32, H_MID / 32), tb>>>(W3, w3t, H_MID, H_LOW);
    transpose_bf16_kernel<<<dim3(DIM / 32,   H_LOW / 32), tb>>>(W4, w4t, H_LOW, DIM);

    ln_kernel<<<MTOT, 256>>>(x, gamma, beta, a0);

    // h1 = gelu(ln @ W1 + b1)   (32768 x 512), K=1024
    gemm_bf16_kernel<false><<<dim3(MTOT / 128, H_MID / 128), 256, GEMM_SMEM>>>(
        a0, w1t, b1, nullptr, a1, DIM, H_MID);
    // h2 = gelu(h1 @ W2 + b2)   (32768 x 512), K=512
    gemm_bf16_kernel<false><<<dim3(MTOT / 128, H_MID / 128), 256, GEMM_SMEM>>>(
        a1, w2t, b2, nullptr, a0, H_MID, H_MID);
    // h3 = gelu(h2 @ W3 + b3)   (32768 x 256), K=512
    gemm_bf16_kernel<false><<<dim3(MTOT / 128, H_LOW / 128), 256, GEMM_SMEM>>>(
        a0, w3t, b3, nullptr, a1, H_MID, H_LOW);
    // out = x + h3 @ W4 + b4    (32768 x 1024), K=256
    gemm_bf16_kernel<true><<<dim3(MTOT / 128, DIM / 128), 256, GEMM_SMEM>>>(
        a1, w4t, b4, x, (float*)d_out, H_LOW, DIM);
}

// round 6
// speedup vs baseline: 1.6896x; 1.0078x over previous
#include <cuda_runtime.h>
#include <cuda_bf16.h>
#include <cstdint>
#include <cstddef>

// ============================================================================
// Problem constants and scratch
// ============================================================================
static constexpr int DIM   = 1024;
static constexpr int H_MID = 512;
static constexpr int H_LOW = 256;
static constexpr int MTOT  = 4 * 8192;  // 32768 tokens

__device__ __nv_bfloat16 g_a0[(size_t)MTOT * DIM];    // ln_out, later h2
__device__ __nv_bfloat16 g_a1[(size_t)MTOT * H_MID];  // h1, later h3
__device__ __nv_bfloat16 g_w1t[H_MID * DIM];
__device__ __nv_bfloat16 g_w2t[H_MID * H_MID];
__device__ __nv_bfloat16 g_w3t[H_LOW * H_MID];
__device__ __nv_bfloat16 g_w4t[DIM * H_LOW];

// ============================================================================
// Helpers
// ============================================================================
__device__ __forceinline__ float gelu_exact(float v) {
    return 0.5f * v * (1.0f + erff(v * 0.70710678118654752440f));
}

__device__ __forceinline__ uint32_t smem_to_u32(const void* p) {
    uint32_t a;
    asm("{ .reg .u64 t; cvta.to.shared.u64 t, %1; cvt.u32.u64 %0, t; }"
        : "=r"(a) : "l"(p));
    return a;
}

__device__ __forceinline__ void cp_async16(uint32_t s, const void* g) {
    asm volatile("cp.async.cg.shared.global [%0], [%1], 16;" :: "r"(s), "l"(g));
}

__device__ __forceinline__ void ldsm_x4(uint32_t (&r)[4], uint32_t addr) {
    asm volatile("ldmatrix.sync.aligned.m8n8.x4.shared.b16 {%0,%1,%2,%3}, [%4];"
                 : "=r"(r[0]), "=r"(r[1]), "=r"(r[2]), "=r"(r[3]) : "r"(addr));
}

__device__ __forceinline__ void mma_bf16(float (&d)[4], const uint32_t (&a)[4],
                                         uint32_t b0, uint32_t b1) {
    asm volatile(
        "mma.sync.aligned.m16n8k16.row.col.f32.bf16.bf16.f32 "
        "{%0,%1,%2,%3},{%4,%5,%6,%7},{%8,%9},{%0,%1,%2,%3};"
        : "+f"(d[0]), "+f"(d[1]), "+f"(d[2]), "+f"(d[3])
        : "r"(a[0]), "r"(a[1]), "r"(a[2]), "r"(a[3]), "r"(b0), "r"(b1));
}

// ============================================================================
// All-weights transpose + bf16 round:  W[K,N] fp32 -> Wt[N,K] bf16
// One launch, flat grid over the 32x32 tiles of all 4 weights.
// ============================================================================
__device__ __forceinline__ void transpose_tile(const float* __restrict__ W,
                                               __nv_bfloat16* __restrict__ Wt,
                                               int K, int N, int tile,
                                               int tx, int ty) {
    __shared__ float t32[32][33];
    const int tilesX = N >> 5;
    const int n0 = (tile % tilesX) * 32, k0 = (tile / tilesX) * 32;
#pragma unroll
    for (int j = 0; j < 32; j += 8)
        t32[ty + j][tx] = W[(size_t)(k0 + ty + j) * N + n0 + tx];
    __syncthreads();
#pragma unroll
    for (int j = 0; j < 32; j += 8)
        Wt[(size_t)(n0 + ty + j) * K + k0 + tx] =
            __float2bfloat16_rn(t32[tx][ty + j]);
}

__global__ void transpose_all_kernel(
    const float* __restrict__ W1, const float* __restrict__ W2,
    const float* __restrict__ W3, const float* __restrict__ W4,
    __nv_bfloat16* __restrict__ w1t, __nv_bfloat16* __restrict__ w2t,
    __nv_bfloat16* __restrict__ w3t, __nv_bfloat16* __restrict__ w4t) {
    const int tx = threadIdx.x, ty = threadIdx.y;  // 32 x 8
    int b = blockIdx.x;
    // tiles: W1 16x32=512, W2 16x16=256, W3 8x16=128, W4 32x8=256  (x=N/32,y=K/32)
    if (b < 512)      { transpose_tile(W1, w1t, DIM,   H_MID, b,       tx, ty); return; }
    b -= 512;
    if (b < 256)      { transpose_tile(W2, w2t, H_MID, H_MID, b,       tx, ty); return; }
    b -= 256;
    if (b < 128)      { transpose_tile(W3, w3t, H_MID, H_LOW, b,       tx, ty); return; }
    b -= 128;
    transpose_tile(W4, w4t, H_LOW, DIM, b, tx, ty);
}

// ============================================================================
// LayerNorm over 1024-wide rows; bf16 output
// ============================================================================
__global__ void __launch_bounds__(256) ln_kernel(const float* __restrict__ x,
                                                 const float* __restrict__ gamma,
                                                 const float* __restrict__ beta,
                                                 __nv_bfloat16* __restrict__ y) {
    __shared__ float red_s[8], red_q[8];
    const int row = blockIdx.x;
    const int t = threadIdx.x;
    const float4 v = (reinterpret_cast<const float4*>(x) + (size_t)row * 256)[t];
    float s = v.x + v.y + v.z + v.w;
    float q = v.x * v.x + v.y * v.y + v.z * v.z + v.w * v.w;
#pragma unroll
    for (int o = 16; o; o >>= 1) {
        s += __shfl_xor_sync(0xffffffffu, s, o);
        q += __shfl_xor_sync(0xffffffffu, q, o);
    }
    if ((t & 31) == 0) { red_s[t >> 5] = s; red_q[t >> 5] = q; }
    __syncthreads();
    float st = 0.f, qt = 0.f;
#pragma unroll
    for (int i = 0; i < 8; i++) { st += red_s[i]; qt += red_q[i]; }
    const float mu = st * (1.0f / 1024.0f);
    const float var = qt * (1.0f / 1024.0f) - mu * mu;
    const float rstd = rsqrtf(var + 1e-5f);
    const float4 g = reinterpret_cast<const float4*>(gamma)[t];
    const float4 b = reinterpret_cast<const float4*>(beta)[t];
    __nv_bfloat162 h01, h23;
    h01.x = __float2bfloat16_rn((v.x - mu) * rstd * g.x + b.x);
    h01.y = __float2bfloat16_rn((v.y - mu) * rstd * g.y + b.y);
    h23.x = __float2bfloat16_rn((v.z - mu) * rstd * g.z + b.z);
    h23.y = __float2bfloat16_rn((v.w - mu) * rstd * g.w + b.w);
    uint2 pk;
    pk.x = *reinterpret_cast<uint32_t*>(&h01);
    pk.y = *reinterpret_cast<uint32_t*>(&h23);
    (reinterpret_cast<uint2*>(y + (size_t)row * 1024))[t] = pk;
}

// ============================================================================
// bf16 mma.sync GEMM:  C[128x128 tile] = A[M,K] @ Bt[N,K]^T (+bias, epilogue)
//   256 threads, 8 warps (4x2), warp tile 32x64, K-tile 64.
//   3-stage cp.async pipeline, ONE __syncthreads per K-tile.
//   Fragments via ldmatrix.x4; smem pitch 144B (conflict-free ldmatrix).
//   RESID=false: out bf16 = gelu(acc + bias)   (feeds next GEMM)
//   RESID=true : out fp32 = acc + bias + resid (final output)
// ============================================================================
static constexpr int PITCH = 144;                       // bytes per smem row
static constexpr int BOFF = 128 * PITCH;                // B tile offset in stage
static constexpr int STAGE_BYTES = 2 * 128 * PITCH;     // 36864
static constexpr int GEMM_SMEM = 3 * STAGE_BYTES;       // 110592

template <bool RESID>
__global__ void __launch_bounds__(256, 2) gemm_bf16_kernel(
    const __nv_bfloat16* __restrict__ A, const __nv_bfloat16* __restrict__ Bt,
    const float* __restrict__ bias, const float* __restrict__ resid,
    void* __restrict__ Cv, int K, int Ntot) {
    extern __shared__ char smem[];
    const uint32_t smem_u = smem_to_u32(smem);
    const int tid = threadIdx.x;
    const int wid = tid >> 5, lane = tid & 31;
    const int wm = wid & 3, wn = wid >> 2;      // 4x2 warps, warp tile 32x64
    const int m0 = blockIdx.x * 128, n0 = blockIdx.y * 128;
    const int NK = K >> 6;                      // K tiles of 64

    const __nv_bfloat16* Abase = A + (size_t)m0 * K;
    const __nv_bfloat16* Bbase = Bt + (size_t)n0 * K;

    const int ldrow = tid >> 3, ldc = (tid & 7) * 16;  // ldc in bytes (8 bf16)
    auto load_tile = [&](int kt, int buf) {
        const uint32_t sb = smem_u + (uint32_t)buf * STAGE_BYTES;
        const int ko = kt * 64;
#pragma unroll
        for (int i = 0; i < 4; i++) {
            const int row = ldrow + i * 32;
            cp_async16(sb + (uint32_t)(row * PITCH) + ldc,
                       Abase + (size_t)row * K + ko + (ldc >> 1));
        }
#pragma unroll
        for (int i = 0; i < 4; i++) {
            const int row = ldrow + i * 32;
            cp_async16(sb + (uint32_t)BOFF + (uint32_t)(row * PITCH) + ldc,
                       Bbase + (size_t)row * K + ko + (ldc >> 1));
        }
        asm volatile("cp.async.commit_group;" ::: "memory");
    };

    float d[2][8][4];
#pragma unroll
    for (int i = 0; i < 2; i++)
#pragma unroll
        for (int j = 0; j < 8; j++)
#pragma unroll
            for (int e = 0; e < 4; e++) d[i][j][e] = 0.0f;

    const uint32_t aOff = (uint32_t)((wm * 32 + (lane & 15)) * PITCH +
                                     ((lane >> 4) & 1) * 16);
    const uint32_t bOff = (uint32_t)BOFF +
        (uint32_t)((wn * 64 + (lane & 7) + ((lane >> 4) & 1) * 8) * PITCH +
                   ((lane >> 3) & 1) * 16);

    load_tile(0, 0);
    load_tile(1, 1);

    for (int kt = 0; kt < NK; kt++) {
        if (kt + 1 < NK) {
            asm volatile("cp.async.wait_group 1;" ::: "memory");
        } else {
            asm volatile("cp.async.wait_group 0;" ::: "memory");
        }
        __syncthreads();
        // Prefetch tile kt+2 into the stage consumed at kt-1 (all warps are
        // past the barrier above, so that stage is free).
        if (kt + 2 < NK) load_tile(kt + 2, (kt + 2) % 3);

        const uint32_t sb = smem_u + (uint32_t)(kt % 3) * STAGE_BYTES;
#pragma unroll
        for (int ks = 0; ks < 4; ks++) {        // 4 x k16 within the 64-K tile
            uint32_t a[2][4], b[4][4];
#pragma unroll
            for (int i = 0; i < 2; i++)
                ldsm_x4(a[i], sb + aOff + (uint32_t)(i * 16 * PITCH + ks * 32));
#pragma unroll
            for (int j2 = 0; j2 < 4; j2++)
                ldsm_x4(b[j2], sb + bOff + (uint32_t)(j2 * 16 * PITCH + ks * 32));
#pragma unroll
            for (int i = 0; i < 2; i++)
#pragma unroll
                for (int j2 = 0; j2 < 4; j2++) {
                    mma_bf16(d[i][2 * j2],     a[i], b[j2][0], b[j2][1]);
                    mma_bf16(d[i][2 * j2 + 1], a[i], b[j2][2], b[j2][3]);
                }
        }
    }

    // ---- Epilogue ----
    const int g = lane >> 2, t2 = (lane & 3) * 2;
#pragma unroll
    for (int i = 0; i < 2; i++) {
        const int r0 = m0 + wm * 32 + i * 16 + g;
#pragma unroll
        for (int j = 0; j < 8; j++) {
            const int cg = n0 + wn * 64 + j * 8 + t2;
            const float bx = bias[cg], by = bias[cg + 1];
            float v0 = d[i][j][0] + bx, v1 = d[i][j][1] + by;
            float v2 = d[i][j][2] + bx, v3 = d[i][j][3] + by;
            if (RESID) {
                float* C = (float*)Cv;
                const float2 x0 = *reinterpret_cast<const float2*>(
                    resid + (size_t)r0 * Ntot + cg);
                const float2 x1 = *reinterpret_cast<const float2*>(
                    resid + (size_t)(r0 + 8) * Ntot + cg);
                *reinterpret_cast<float2*>(C + (size_t)r0 * Ntot + cg) =
                    make_float2(v0 + x0.x, v1 + x0.y);
                *reinterpret_cast<float2*>(C + (size_t)(r0 + 8) * Ntot + cg) =
                    make_float2(v2 + x1.x, v3 + x1.y);
            } else {
                __nv_bfloat16* C = (__nv_bfloat16*)Cv;
                __nv_bfloat162 p0, p1;
                p0.x = __float2bfloat16_rn(gelu_exact(v0));
                p0.y = __float2bfloat16_rn(gelu_exact(v1));
                p1.x = __float2bfloat16_rn(gelu_exact(v2));
                p1.y = __float2bfloat16_rn(gelu_exact(v3));
                *reinterpret_cast<__nv_bfloat162*>(C + (size_t)r0 * Ntot + cg) = p0;
                *reinterpret_cast<__nv_bfloat162*>(C + (size_t)(r0 + 8) * Ntot + cg) = p1;
            }
        }
    }
}

// ============================================================================
// kernel_launch
// ============================================================================
extern "C" void kernel_launch(void* const* d_in, const int* in_sizes, int n_in,
                              void* d_out, int out_size) {
    const float* x     = (const float*)d_in[0];
    const float* gamma = (const float*)d_in[1];
    const float* beta  = (const float*)d_in[2];
    const float* W1    = (const float*)d_in[3];
    const float* b1    = (const float*)d_in[4];
    const float* W2    = (const float*)d_in[5];
    const float* b2    = (const float*)d_in[6];
    const float* W3    = (const float*)d_in[7];
    const float* b3    = (const float*)d_in[8];
    const float* W4    = (const float*)d_in[9];
    const float* b4    = (const float*)d_in[10];

    __nv_bfloat16 *a0, *a1, *w1t, *w2t, *w3t, *w4t;
    cudaGetSymbolAddress((void**)&a0, g_a0);
    cudaGetSymbolAddress((void**)&a1, g_a1);
    cudaGetSymbolAddress((void**)&w1t, g_w1t);
    cudaGetSymbolAddress((void**)&w2t, g_w2t);
    cudaGetSymbolAddress((void**)&w3t, g_w3t);
    cudaGetSymbolAddress((void**)&w4t, g_w4t);

    cudaFuncSetAttribute(gemm_bf16_kernel<false>,
                         cudaFuncAttributeMaxDynamicSharedMemorySize, GEMM_SMEM);
    cudaFuncSetAttribute(gemm_bf16_kernel<true>,
                         cudaFuncAttributeMaxDynamicSharedMemorySize, GEMM_SMEM);

    transpose_all_kernel<<<1152, dim3(32, 8)>>>(W1, W2, W3, W4,
                                                w1t, w2t, w3t, w4t);
    ln_kernel<<<MTOT, 256>>>(x, gamma, beta, a0);

    // h1 = gelu(ln @ W1 + b1)   (32768 x 512), K=1024
    gemm_bf16_kernel<false><<<dim3(MTOT / 128, H_MID / 128), 256, GEMM_SMEM>>>(
        a0, w1t, b1, nullptr, a1, DIM, H_MID);
    // h2 = gelu(h1 @ W2 + b2)   (32768 x 512), K=512
    gemm_bf16_kernel<false><<<dim3(MTOT / 128, H_MID / 128), 256, GEMM_SMEM>>>(
        a1, w2t, b2, nullptr, a0, H_MID, H_MID);
    // h3 = gelu(h2 @ W3 + b3)   (32768 x 256), K=512
    gemm_bf16_kernel<false><<<dim3(MTOT / 128, H_LOW / 128), 256, GEMM_SMEM>>>(
        a0, w3t, b3, nullptr, a1, H_MID, H_LOW);
    // out = x + h3 @ W4 + b4    (32768 x 1024), K=256
    gemm_bf16_kernel<true><<<dim3(MTOT / 128, DIM / 128), 256, GEMM_SMEM>>>(
        a1, w4t, b4, x, (float*)d_out, H_LOW, DIM);
}

// round 12
// speedup vs baseline: 1.7440x; 1.0322x over previous
#include <cuda_runtime.h>
#include <cuda_bf16.h>
#include <cstdint>
#include <cstddef>

// ============================================================================
// Problem constants and scratch
// ============================================================================
static constexpr int DIM   = 1024;
static constexpr int H_MID = 512;
static constexpr int H_LOW = 256;
static constexpr int MTOT  = 4 * 8192;  // 32768 tokens

__device__ __nv_bfloat16 g_a0[(size_t)MTOT * DIM];    // ln_out, later h2
__device__ __nv_bfloat16 g_a1[(size_t)MTOT * H_MID];  // h1, later h3
__device__ __nv_bfloat16 g_w1t[H_MID * DIM];
__device__ __nv_bfloat16 g_w2t[H_MID * H_MID];
__device__ __nv_bfloat16 g_w3t[H_LOW * H_MID];
__device__ __nv_bfloat16 g_w4t[DIM * H_LOW];

// ============================================================================
// Helpers
// ============================================================================
__device__ __forceinline__ float gelu_exact(float v) {
    return 0.5f * v * (1.0f + erff(v * 0.70710678118654752440f));
}

__device__ __forceinline__ uint32_t smem_to_u32(const void* p) {
    uint32_t a;
    asm("{ .reg .u64 t; cvta.to.shared.u64 t, %1; cvt.u32.u64 %0, t; }"
        : "=r"(a) : "l"(p));
    return a;
}

__device__ __forceinline__ void cp_async16(uint32_t s, const void* g) {
    asm volatile("cp.async.cg.shared.global [%0], [%1], 16;" :: "r"(s), "l"(g));
}

__device__ __forceinline__ void ldsm_x4(uint32_t (&r)[4], uint32_t addr) {
    asm volatile("ldmatrix.sync.aligned.m8n8.x4.shared.b16 {%0,%1,%2,%3}, [%4];"
                 : "=r"(r[0]), "=r"(r[1]), "=r"(r[2]), "=r"(r[3]) : "r"(addr));
}

__device__ __forceinline__ void mma_bf16(float (&d)[4], const uint32_t (&a)[4],
                                         uint32_t b0, uint32_t b1) {
    asm volatile(
        "mma.sync.aligned.m16n8k16.row.col.f32.bf16.bf16.f32 "
        "{%0,%1,%2,%3},{%4,%5,%6,%7},{%8,%9},{%0,%1,%2,%3};"
        : "+f"(d[0]), "+f"(d[1]), "+f"(d[2]), "+f"(d[3])
        : "r"(a[0]), "r"(a[1]), "r"(a[2]), "r"(a[3]), "r"(b0), "r"(b1));
}

// ============================================================================
// All-weights transpose + bf16 round:  W[K,N] fp32 -> Wt[N,K] bf16
// One launch, flat grid over the 32x32 tiles of all 4 weights.
// (Structure identical to the round-6 kernel that measured passing.)
// ============================================================================
__device__ __forceinline__ void transpose_tile(const float* __restrict__ W,
                                               __nv_bfloat16* __restrict__ Wt,
                                               int K, int N, int tile,
                                               int tx, int ty) {
    __shared__ float t32[32][33];
    const int tilesX = N >> 5;
    const int n0 = (tile % tilesX) * 32, k0 = (tile / tilesX) * 32;
#pragma unroll
    for (int j = 0; j < 32; j += 8)
        t32[ty + j][tx] = W[(size_t)(k0 + ty + j) * N + n0 + tx];
    __syncthreads();
#pragma unroll
    for (int j = 0; j < 32; j += 8)
        Wt[(size_t)(n0 + ty + j) * K + k0 + tx] =
            __float2bfloat16_rn(t32[tx][ty + j]);
}

__global__ void transpose_all_kernel(
    const float* __restrict__ W1, const float* __restrict__ W2,
    const float* __restrict__ W3, const float* __restrict__ W4,
    __nv_bfloat16* __restrict__ w1t, __nv_bfloat16* __restrict__ w2t,
    __nv_bfloat16* __restrict__ w3t, __nv_bfloat16* __restrict__ w4t) {
    const int tx = threadIdx.x, ty = threadIdx.y;  // 32 x 8
    int b = blockIdx.x;
    // tiles: W1 16x32=512, W2 16x16=256, W3 8x16=128, W4 32x8=256
    if (b < 512) { transpose_tile(W1, w1t, DIM,   H_MID, b, tx, ty); return; }
    b -= 512;
    if (b < 256) { transpose_tile(W2, w2t, H_MID, H_MID, b, tx, ty); return; }
    b -= 256;
    if (b < 128) { transpose_tile(W3, w3t, H_MID, H_LOW, b, tx, ty); return; }
    b -= 128;
    transpose_tile(W4, w4t, H_LOW, DIM, b, tx, ty);
}

// ============================================================================
// LayerNorm: warp-per-row (8 rows per 256-thread block), MLP=8 per thread,
// shuffle-only reduction, values kept in registers for the normalize pass.
// ============================================================================
__global__ void __launch_bounds__(256) ln_kernel(const float* __restrict__ x,
                                                 const float* __restrict__ gamma,
                                                 const float* __restrict__ beta,
                                                 __nv_bfloat16* __restrict__ y) {
    const int tx = threadIdx.x & 31;
    const int ty = threadIdx.x >> 5;
    const int row = blockIdx.x * 8 + ty;
    const float4* xr = reinterpret_cast<const float4*>(x) + (size_t)row * 256;
    float4 v[8];
    float s = 0.f, q = 0.f;
#pragma unroll
    for (int i = 0; i < 8; i++) {
        v[i] = xr[tx + i * 32];
        s += v[i].x + v[i].y + v[i].z + v[i].w;
        q += v[i].x * v[i].x + v[i].y * v[i].y +
             v[i].z * v[i].z + v[i].w * v[i].w;
    }
#pragma unroll
    for (int o = 16; o; o >>= 1) {
        s += __shfl_xor_sync(0xffffffffu, s, o);
        q += __shfl_xor_sync(0xffffffffu, q, o);
    }
    const float mu = s * (1.0f / 1024.0f);
    const float var = q * (1.0f / 1024.0f) - mu * mu;
    const float rstd = rsqrtf(var + 1e-5f);
    uint2* yr = reinterpret_cast<uint2*>(y + (size_t)row * 1024);
#pragma unroll
    for (int i = 0; i < 8; i++) {
        const int c4 = tx + i * 32;
        const float4 g = reinterpret_cast<const float4*>(gamma)[c4];
        const float4 bb = reinterpret_cast<const float4*>(beta)[c4];
        __nv_bfloat162 h01, h23;
        h01.x = __float2bfloat16_rn((v[i].x - mu) * rstd * g.x + bb.x);
        h01.y = __float2bfloat16_rn((v[i].y - mu) * rstd * g.y + bb.y);
        h23.x = __float2bfloat16_rn((v[i].z - mu) * rstd * g.z + bb.z);
        h23.y = __float2bfloat16_rn((v[i].w - mu) * rstd * g.w + bb.w);
        uint2 pk;
        pk.x = *reinterpret_cast<uint32_t*>(&h01);
        pk.y = *reinterpret_cast<uint32_t*>(&h23);
        yr[c4] = pk;
    }
}

// ============================================================================
// bf16 mma.sync GEMM:  C[128x128 tile] = A[M,K] @ Bt[N,K]^T (+bias, epilogue)
//   256 threads, 8 warps (4x2), warp tile 32x64, K-tile 64.
//   3-stage cp.async pipeline, ONE __syncthreads per K-tile.
//   RESID=false: out bf16 = gelu(acc + bias)   (feeds next GEMM)
//   RESID=true : out fp32 = acc + bias + resid (final output)
// (Byte-identical to the measured 349.7us version.)
// ============================================================================
static constexpr int PITCH = 144;                       // bytes per smem row
static constexpr int BOFF = 128 * PITCH;                // B tile offset in stage
static constexpr int STAGE_BYTES = 2 * 128 * PITCH;     // 36864
static constexpr int GEMM_SMEM = 3 * STAGE_BYTES;       // 110592

template <bool RESID>
__global__ void __launch_bounds__(256, 2) gemm_bf16_kernel(
    const __nv_bfloat16* __restrict__ A, const __nv_bfloat16* __restrict__ Bt,
    const float* __restrict__ bias, const float* __restrict__ resid,
    void* __restrict__ Cv, int K, int Ntot) {
    extern __shared__ char smem[];
    const uint32_t smem_u = smem_to_u32(smem);
    const int tid = threadIdx.x;
    const int wid = tid >> 5, lane = tid & 31;
    const int wm = wid & 3, wn = wid >> 2;      // 4x2 warps, warp tile 32x64
    const int m0 = blockIdx.x * 128, n0 = blockIdx.y * 128;
    const int NK = K >> 6;                      // K tiles of 64

    const __nv_bfloat16* Abase = A + (size_t)m0 * K;
    const __nv_bfloat16* Bbase = Bt + (size_t)n0 * K;

    const int ldrow = tid >> 3, ldc = (tid & 7) * 16;  // ldc in bytes (8 bf16)
    auto load_tile = [&](int kt, int buf) {
        const uint32_t sb = smem_u + (uint32_t)buf * STAGE_BYTES;
        const int ko = kt * 64;
#pragma unroll
        for (int i = 0; i < 4; i++) {
            const int row = ldrow + i * 32;
            cp_async16(sb + (uint32_t)(row * PITCH) + ldc,
                       Abase + (size_t)row * K + ko + (ldc >> 1));
        }
#pragma unroll
        for (int i = 0; i < 4; i++) {
            const int row = ldrow + i * 32;
            cp_async16(sb + (uint32_t)BOFF + (uint32_t)(row * PITCH) + ldc,
                       Bbase + (size_t)row * K + ko + (ldc >> 1));
        }
        asm volatile("cp.async.commit_group;" ::: "memory");
    };

    float d[2][8][4];
#pragma unroll
    for (int i = 0; i < 2; i++)
#pragma unroll
        for (int j = 0; j < 8; j++)
#pragma unroll
            for (int e = 0; e < 4; e++) d[i][j][e] = 0.0f;

    const uint32_t aOff = (uint32_t)((wm * 32 + (lane & 15)) * PITCH +
                                     ((lane >> 4) & 1) * 16);
    const uint32_t bOff = (uint32_t)BOFF +
        (uint32_t)((wn * 64 + (lane & 7) + ((lane >> 4) & 1) * 8) * PITCH +
                   ((lane >> 3) & 1) * 16);

    load_tile(0, 0);
    load_tile(1, 1);

    for (int kt = 0; kt < NK; kt++) {
        if (kt + 1 < NK) {
            asm volatile("cp.async.wait_group 1;" ::: "memory");
        } else {
            asm volatile("cp.async.wait_group 0;" ::: "memory");
        }
        __syncthreads();
        if (kt + 2 < NK) load_tile(kt + 2, (kt + 2) % 3);

        const uint32_t sb = smem_u + (uint32_t)(kt % 3) * STAGE_BYTES;
#pragma unroll
        for (int ks = 0; ks < 4; ks++) {        // 4 x k16 within the 64-K tile
            uint32_t a[2][4], b[4][4];
#pragma unroll
            for (int i = 0; i < 2; i++)
                ldsm_x4(a[i], sb + aOff + (uint32_t)(i * 16 * PITCH + ks * 32));
#pragma unroll
            for (int j2 = 0; j2 < 4; j2++)
                ldsm_x4(b[j2], sb + bOff + (uint32_t)(j2 * 16 * PITCH + ks * 32));
#pragma unroll
            for (int i = 0; i < 2; i++)
#pragma unroll
                for (int j2 = 0; j2 < 4; j2++) {
                    mma_bf16(d[i][2 * j2],     a[i], b[j2][0], b[j2][1]);
                    mma_bf16(d[i][2 * j2 + 1], a[i], b[j2][2], b[j2][3]);
                }
        }
    }

    // ---- Epilogue ----
    const int g = lane >> 2, t2 = (lane & 3) * 2;
#pragma unroll
    for (int i = 0; i < 2; i++) {
        const int r0 = m0 + wm * 32 + i * 16 + g;
#pragma unroll
        for (int j = 0; j < 8; j++) {
            const int cg = n0 + wn * 64 + j * 8 + t2;
            const float bx = bias[cg], by = bias[cg + 1];
            float v0 = d[i][j][0] + bx, v1 = d[i][j][1] + by;
            float v2 = d[i][j][2] + bx, v3 = d[i][j][3] + by;
            if (RESID) {
                float* C = (float*)Cv;
                const float2 x0 = *reinterpret_cast<const float2*>(
                    resid + (size_t)r0 * Ntot + cg);
                const float2 x1 = *reinterpret_cast<const float2*>(
                    resid + (size_t)(r0 + 8) * Ntot + cg);
                *reinterpret_cast<float2*>(C + (size_t)r0 * Ntot + cg) =
                    make_float2(v0 + x0.x, v1 + x0.y);
                *reinterpret_cast<float2*>(C + (size_t)(r0 + 8) * Ntot + cg) =
                    make_float2(v2 + x1.x, v3 + x1.y);
            } else {
                __nv_bfloat16* C = (__nv_bfloat16*)Cv;
                __nv_bfloat162 p0, p1;
                p0.x = __float2bfloat16_rn(gelu_exact(v0));
                p0.y = __float2bfloat16_rn(gelu_exact(v1));
                p1.x = __float2bfloat16_rn(gelu_exact(v2));
                p1.y = __float2bfloat16_rn(gelu_exact(v3));
                *reinterpret_cast<__nv_bfloat162*>(C + (size_t)r0 * Ntot + cg) = p0;
                *reinterpret_cast<__nv_bfloat162*>(C + (size_t)(r0 + 8) * Ntot + cg) = p1;
            }
        }
    }
}

// ============================================================================
// kernel_launch
// ============================================================================
extern "C" void kernel_launch(void* const* d_in, const int* in_sizes, int n_in,
                              void* d_out, int out_size) {
    const float* x     = (const float*)d_in[0];
    const float* gamma = (const float*)d_in[1];
    const float* beta  = (const float*)d_in[2];
    const float* W1    = (const float*)d_in[3];
    const float* b1    = (const float*)d_in[4];
    const float* W2    = (const float*)d_in[5];
    const float* b2    = (const float*)d_in[6];
    const float* W3    = (const float*)d_in[7];
    const float* b3    = (const float*)d_in[8];
    const float* W4    = (const float*)d_in[9];
    const float* b4    = (const float*)d_in[10];

    __nv_bfloat16 *a0, *a1, *w1t, *w2t, *w3t, *w4t;
    cudaGetSymbolAddress((void**)&a0, g_a0);
    cudaGetSymbolAddress((void**)&a1, g_a1);
    cudaGetSymbolAddress((void**)&w1t, g_w1t);
    cudaGetSymbolAddress((void**)&w2t, g_w2t);
    cudaGetSymbolAddress((void**)&w3t, g_w3t);
    cudaGetSymbolAddress((void**)&w4t, g_w4t);

    cudaFuncSetAttribute(gemm_bf16_kernel<false>,
                         cudaFuncAttributeMaxDynamicSharedMemorySize, GEMM_SMEM);
    cudaFuncSetAttribute(gemm_bf16_kernel<true>,
                         cudaFuncAttributeMaxDynamicSharedMemorySize, GEMM_SMEM);

    transpose_all_kernel<<<1152, dim3(32, 8)>>>(W1, W2, W3, W4,
                                                w1t, w2t, w3t, w4t);
    ln_kernel<<<MTOT / 8, 256>>>(x, gamma, beta, a0);

    // h1 = gelu(ln @ W1 + b1)   (32768 x 512), K=1024
    gemm_bf16_kernel<false><<<dim3(MTOT / 128, H_MID / 128), 256, GEMM_SMEM>>>(
        a0, w1t, b1, nullptr, a1, DIM, H_MID);
    // h2 = gelu(h1 @ W2 + b2)   (32768 x 512), K=512
    gemm_bf16_kernel<false><<<dim3(MTOT / 128, H_MID / 128), 256, GEMM_SMEM>>>(
        a1, w2t, b2, nullptr, a0, H_MID, H_MID);
    // h3 = gelu(h2 @ W3 + b3)   (32768 x 256), K=512
    gemm_bf16_kernel<false><<<dim3(MTOT / 128, H_LOW / 128), 256, GEMM_SMEM>>>(
        a0, w3t, b3, nullptr, a1, H_MID, H_LOW);
    // out = x + h3 @ W4 + b4    (32768 x 1024), K=256
    gemm_bf16_kernel<true><<<dim3(MTOT / 128, DIM / 128), 256, GEMM_SMEM>>>(
        a1, w4t, b4, x, (float*)d_out, H_LOW, DIM);
}